// round 1
// baseline (speedup 1.0000x reference)
#include <cuda_runtime.h>
#include <math.h>

// NeuralField: fused hashgrid encode + 4-layer MLP, fp32 baseline.
// CTA = 64 points, 256 threads. Activations live entirely in SMEM.

#define NLEV   8
#define NPTS   262144
#define TILE   64         // points per CTA
#define PITCH  257        // SMEM activation pitch (odd -> conflict-free col reads)
#define KC     32         // K-chunk of weights staged in SMEM

struct LevelParams { float scale[NLEV]; int res[NLEV]; int size[NLEV]; };

// SMEM: hA[64*257] + hB[64*257] + Bs[32*256] + W3s[256]
#define SMEM_FLOATS (2*TILE*PITCH + KC*256 + 256)
#define SMEM_BYTES  (SMEM_FLOATS * 4)

__global__ __launch_bounds__(256, 1)
void nf_kernel(const float* __restrict__ x, const float* __restrict__ table,
               const float* __restrict__ W0, const float* __restrict__ W1,
               const float* __restrict__ W2, const float* __restrict__ W3,
               float* __restrict__ out, LevelParams lp)
{
    extern __shared__ float smem[];
    float* hA  = smem;                   // [64][257]
    float* hB  = hA + TILE * PITCH;      // [64][257]
    float* Bs  = hB + TILE * PITCH;      // [32][256]
    float* W3s = Bs + KC * 256;          // [256]

    const int tid = threadIdx.x;
    const int tx  = tid & 31;            // col group (0..31)
    const int ty  = tid >> 5;            // row group (0..7)

    W3s[tid] = W3[tid];                  // 256 threads, 256 weights

    // ---------------- Encode: 4 threads/point, 2 levels/thread --------------
    {
        const int p    = tid & 63;       // local point
        const int pair = tid >> 6;       // 0..3 -> levels {2p, 2p+1}
        const int gp   = blockIdx.x * TILE + p;
        const float xx = x[2 * gp];
        const float yy = x[2 * gp + 1];

        #pragma unroll
        for (int li = 0; li < 2; ++li) {
            const int l     = pair * 2 + li;
            const float s   = lp.scale[l];
            const int res   = lp.res[l];
            const int size  = lp.size[l];

            const float posx = xx * s + 0.5f;
            const float posy = yy * s + 0.5f;
            const float gx = floorf(posx), gy = floorf(posy);
            const float fx = posx - gx,    fy = posy - gy;
            const int   ix = (int)gx,      iy = (int)gy;
            const float wx = fx * fx * (3.0f - 2.0f * fx);
            const float wy = fy * fy * (3.0f - 2.0f * fy);

            float f[8];
            #pragma unroll
            for (int j = 0; j < 8; ++j) f[j] = 0.0f;

            #pragma unroll
            for (int dx = 0; dx < 2; ++dx) {
                const float wxx = dx ? wx : (1.0f - wx);
                #pragma unroll
                for (int dy = 0; dy < 2; ++dy) {
                    const float wyy = dy ? wy : (1.0f - wy);
                    const int idx = ((ix + dx) + (iy + dy) * res) % size;
                    const float4* tp =
                        (const float4*)(table + ((size_t)(l * 8192 + idx) << 3));
                    const float w = wxx * wyy;
                    const float4 t0 = tp[0];
                    const float4 t1 = tp[1];
                    f[0] += w * t0.x; f[1] += w * t0.y;
                    f[2] += w * t0.z; f[3] += w * t0.w;
                    f[4] += w * t1.x; f[5] += w * t1.y;
                    f[6] += w * t1.z; f[7] += w * t1.w;
                }
            }
            #pragma unroll
            for (int j = 0; j < 8; ++j)
                hA[p * PITCH + l * 8 + j] = f[j];
        }
    }
    __syncthreads();

    // ---------------- Layers 0..2: [64,K] @ [K,256] + ReLU -------------------
    float acc[8][8];
    for (int layer = 0; layer < 3; ++layer) {
        const float* As = (layer == 1) ? hB : hA;
        float*       Cs = (layer == 1) ? hA : hB;
        const float* Wg = (layer == 0) ? W0 : ((layer == 1) ? W1 : W2);
        const int    K  = (layer == 0) ? 64 : 256;

        #pragma unroll
        for (int r = 0; r < 8; ++r)
            #pragma unroll
            for (int c = 0; c < 8; ++c) acc[r][c] = 0.0f;

        for (int k0 = 0; k0 < K; k0 += KC) {
            __syncthreads();   // protect Bs from previous chunk's readers
            // stage W[k0:k0+32, 0:256] into SMEM (coalesced float4)
            const float4* Wv  = (const float4*)(Wg + k0 * 256);
            float4*       Bsv = (float4*)Bs;
            #pragma unroll
            for (int j = 0; j < 8; ++j)
                Bsv[tid + 256 * j] = Wv[tid + 256 * j];
            __syncthreads();

            #pragma unroll 4
            for (int k = 0; k < KC; ++k) {
                float a[8], b[8];
                #pragma unroll
                for (int r = 0; r < 8; ++r)
                    a[r] = As[(ty * 8 + r) * PITCH + k0 + k];   // warp broadcast
                #pragma unroll
                for (int c = 0; c < 8; ++c)
                    b[c] = Bs[k * 256 + tx + 32 * c];           // conflict-free
                #pragma unroll
                for (int r = 0; r < 8; ++r)
                    #pragma unroll
                    for (int c = 0; c < 8; ++c)
                        acc[r][c] = fmaf(a[r], b[c], acc[r][c]);
            }
        }
        __syncthreads();
        #pragma unroll
        for (int r = 0; r < 8; ++r)
            #pragma unroll
            for (int c = 0; c < 8; ++c)
                Cs[(ty * 8 + r) * PITCH + tx + 32 * c] = fmaxf(acc[r][c], 0.0f);
        __syncthreads();
    }

    // ---------------- Layer 3: [64,256] @ [256,1] ----------------------------
    if (tid < TILE) {
        const float* h = hB + tid * PITCH;   // pitch 257 -> conflict-free
        float s = 0.0f;
        #pragma unroll 8
        for (int k = 0; k < 256; ++k)
            s = fmaf(h[k], W3s[k], s);
        out[blockIdx.x * TILE + tid] = s;
    }
}

extern "C" void kernel_launch(void* const* d_in, const int* in_sizes, int n_in,
                              void* d_out, int out_size)
{
    const float* x     = (const float*)d_in[0];
    const float* table = (const float*)d_in[1];
    const float* W0    = (const float*)d_in[2];
    const float* W1    = (const float*)d_in[3];
    const float* W2    = (const float*)d_in[4];
    const float* W3    = (const float*)d_in[5];
    float*       out   = (float*)d_out;

    // Level params in double, mirroring the numpy reference exactly.
    LevelParams lp;
    for (int l = 0; l < NLEV; ++l) {
        double sc = 16.0 * pow(1.2599210739135742, (double)l) - 1.0;
        int res = (int)ceil(sc) + 1;
        long long sz = (long long)res * (long long)res;
        sz = ((sz + 7) / 8) * 8;
        if (sz > (1LL << 19)) sz = 1LL << 19;
        lp.scale[l] = (float)sc;
        lp.res[l]   = res;
        lp.size[l]  = (int)sz;
    }

    cudaFuncSetAttribute(nf_kernel, cudaFuncAttributeMaxDynamicSharedMemorySize,
                         SMEM_BYTES);
    nf_kernel<<<NPTS / TILE, 256, SMEM_BYTES>>>(x, table, W0, W1, W2, W3, out, lp);
}

// round 2
// speedup vs baseline: 1.1081x; 1.1081x over previous
#include <cuda_runtime.h>
#include <math.h>

// NeuralField: fused hashgrid encode + 4-layer MLP.
// Round 2: packed fma.rn.f32x2 (FFMA2) mainloop — 2 FMAs per issue slot,
// accumulating even-k in .lo and odd-k in .hi, final horizontal add.

#define NLEV   8
#define NPTS   262144
#define TILE   64         // points per CTA
#define PITCH  258        // even -> 8B-aligned float2 k-pair loads
#define KC     32         // K-chunk of weights staged in SMEM

struct LevelParams { float scale[NLEV]; int res[NLEV]; int size[NLEV]; };

// SMEM: hA[64*258] + hB[64*258] + Bs[32*256] + W3s[256]
#define SMEM_FLOATS (2*TILE*PITCH + KC*256 + 256)
#define SMEM_BYTES  (SMEM_FLOATS * 4)

typedef unsigned long long u64;

__device__ __forceinline__ u64 pack2(float lo, float hi) {
    u64 r;
    asm("mov.b64 %0, {%1, %2};" : "=l"(r) : "f"(lo), "f"(hi));
    return r;
}
__device__ __forceinline__ void ffma2(u64& d, u64 a, u64 b) {
    asm("fma.rn.f32x2 %0, %1, %2, %0;" : "+l"(d) : "l"(a), "l"(b));
}
__device__ __forceinline__ float hadd2(u64 v) {
    float lo, hi;
    asm("mov.b64 {%0, %1}, %2;" : "=f"(lo), "=f"(hi) : "l"(v));
    return lo + hi;
}

__global__ __launch_bounds__(256, 1)
void nf_kernel(const float* __restrict__ x, const float* __restrict__ table,
               const float* __restrict__ W0, const float* __restrict__ W1,
               const float* __restrict__ W2, const float* __restrict__ W3,
               float* __restrict__ out, LevelParams lp)
{
    extern __shared__ float smem[];
    float* hA  = smem;                   // [64][258]
    float* hB  = hA + TILE * PITCH;      // [64][258]
    float* Bs  = hB + TILE * PITCH;      // [32][256]
    float* W3s = Bs + KC * 256;          // [256]

    const int tid = threadIdx.x;
    const int tx  = tid & 31;            // lane -> output column group
    const int ty  = tid >> 5;            // warp -> row group

    W3s[tid] = W3[tid];

    // ---------------- Encode: 4 threads/point, 2 levels/thread --------------
    {
        const int p    = tid & 63;
        const int pair = tid >> 6;       // 0..3 -> levels {2p, 2p+1}
        const int gp   = blockIdx.x * TILE + p;
        const float xx = x[2 * gp];
        const float yy = x[2 * gp + 1];

        #pragma unroll
        for (int li = 0; li < 2; ++li) {
            const int l     = pair * 2 + li;
            const float s   = lp.scale[l];
            const int res   = lp.res[l];
            const int size  = lp.size[l];

            const float posx = xx * s + 0.5f;
            const float posy = yy * s + 0.5f;
            const float gx = floorf(posx), gy = floorf(posy);
            const float fx = posx - gx,    fy = posy - gy;
            const int   ix = (int)gx,      iy = (int)gy;
            const float wx = fx * fx * (3.0f - 2.0f * fx);
            const float wy = fy * fy * (3.0f - 2.0f * fy);

            float f[8];
            #pragma unroll
            for (int j = 0; j < 8; ++j) f[j] = 0.0f;

            #pragma unroll
            for (int dx = 0; dx < 2; ++dx) {
                const float wxx = dx ? wx : (1.0f - wx);
                #pragma unroll
                for (int dy = 0; dy < 2; ++dy) {
                    const float wyy = dy ? wy : (1.0f - wy);
                    const int idx = ((ix + dx) + (iy + dy) * res) % size;
                    const float4* tp =
                        (const float4*)(table + ((size_t)(l * 8192 + idx) << 3));
                    const float w = wxx * wyy;
                    const float4 t0 = tp[0];
                    const float4 t1 = tp[1];
                    f[0] += w * t0.x; f[1] += w * t0.y;
                    f[2] += w * t0.z; f[3] += w * t0.w;
                    f[4] += w * t1.x; f[5] += w * t1.y;
                    f[6] += w * t1.z; f[7] += w * t1.w;
                }
            }
            #pragma unroll
            for (int j = 0; j < 8; ++j)
                hA[p * PITCH + l * 8 + j] = f[j];
        }
    }
    __syncthreads();

    // ---------------- Layers 0..2: [64,K] @ [K,256] + ReLU -------------------
    u64 acc2[8][8];
    for (int layer = 0; layer < 3; ++layer) {
        const float* As = (layer == 1) ? hB : hA;
        float*       Cs = (layer == 1) ? hA : hB;
        const float* Wg = (layer == 0) ? W0 : ((layer == 1) ? W1 : W2);
        const int    K  = (layer == 0) ? 64 : 256;

        #pragma unroll
        for (int r = 0; r < 8; ++r)
            #pragma unroll
            for (int c = 0; c < 8; ++c) acc2[r][c] = 0ULL;

        for (int k0 = 0; k0 < K; k0 += KC) {
            __syncthreads();   // protect Bs from previous chunk's readers
            // stage W[k0:k0+32, 0:256] into SMEM (coalesced float4)
            const float4* Wv  = (const float4*)(Wg + k0 * 256);
            float4*       Bsv = (float4*)Bs;
            #pragma unroll
            for (int j = 0; j < 8; ++j)
                Bsv[tid + 256 * j] = Wv[tid + 256 * j];
            __syncthreads();

            #pragma unroll 4
            for (int k = 0; k < KC; k += 2) {
                u64 a2[8];
                #pragma unroll
                for (int r = 0; r < 8; ++r) {
                    const float2 av =
                        *(const float2*)&As[(ty * 8 + r) * PITCH + k0 + k];
                    a2[r] = pack2(av.x, av.y);          // warp broadcast LDS.64
                }
                #pragma unroll
                for (int c = 0; c < 8; ++c) {
                    const float blo = Bs[k * 256 + tx + 32 * c];
                    const float bhi = Bs[(k + 1) * 256 + tx + 32 * c];
                    const u64 b2 = pack2(blo, bhi);
                    #pragma unroll
                    for (int r = 0; r < 8; ++r)
                        ffma2(acc2[r][c], a2[r], b2);   // FFMA2: 2 FMAs/slot
                }
            }
        }
        __syncthreads();
        #pragma unroll
        for (int r = 0; r < 8; ++r)
            #pragma unroll
            for (int c = 0; c < 8; ++c)
                Cs[(ty * 8 + r) * PITCH + tx + 32 * c] =
                    fmaxf(hadd2(acc2[r][c]), 0.0f);
        __syncthreads();
    }

    // ---------------- Layer 3: [64,256] @ [256,1] ----------------------------
    if (tid < TILE) {
        const float* h = hB + tid * PITCH;
        float s = 0.0f;
        #pragma unroll 8
        for (int k = 0; k < 256; ++k)
            s = fmaf(h[k], W3s[k], s);
        out[blockIdx.x * TILE + tid] = s;
    }
}

extern "C" void kernel_launch(void* const* d_in, const int* in_sizes, int n_in,
                              void* d_out, int out_size)
{
    const float* x     = (const float*)d_in[0];
    const float* table = (const float*)d_in[1];
    const float* W0    = (const float*)d_in[2];
    const float* W1    = (const float*)d_in[3];
    const float* W2    = (const float*)d_in[4];
    const float* W3    = (const float*)d_in[5];
    float*       out   = (float*)d_out;

    LevelParams lp;
    for (int l = 0; l < NLEV; ++l) {
        double sc = 16.0 * pow(1.2599210739135742, (double)l) - 1.0;
        int res = (int)ceil(sc) + 1;
        long long sz = (long long)res * (long long)res;
        sz = ((sz + 7) / 8) * 8;
        if (sz > (1LL << 19)) sz = 1LL << 19;
        lp.scale[l] = (float)sc;
        lp.res[l]   = res;
        lp.size[l]  = (int)sz;
    }

    cudaFuncSetAttribute(nf_kernel, cudaFuncAttributeMaxDynamicSharedMemorySize,
                         SMEM_BYTES);
    nf_kernel<<<NPTS / TILE, 256, SMEM_BYTES>>>(x, table, W0, W1, W2, W3, out, lp);
}

// round 4
// speedup vs baseline: 2.7082x; 2.4440x over previous
#include <cuda_runtime.h>
#include <cstdint>
#include <math.h>

// NeuralField fused: hashgrid encode + 3-layer MLP on mma.sync TF32 tensor
// cores (baseline PTX -> assembles for sm_103 target), + fused final dot.
// CTA = 64 points, 256 threads (8 warps). Warp w owns output cols [32w,32w+32).
// Weights pre-rounded to tf32 in a prep kernel, streamed via cp.async
// double-buffer in 32-row chunks.

#define NLEV    8
#define NPTS    262144
#define THREADS 256

// SMEM float offsets
#define HA_PITCH 68
#define HB_PITCH 260
#define HA_OFF   0
#define B1_OFF   (HA_OFF + 64 * HA_PITCH)          // 4352
#define B2_OFF   (B1_OFF + 64 * HB_PITCH)          // +16640
#define BS_OFF   (B2_OFF + 64 * HB_PITCH)          // +16640
#define BS_F     (32 * HB_PITCH)                   // 8320 floats per buffer
#define W3_OFF   (BS_OFF + 2 * BS_F)
#define SMEM_FLOATS (W3_OFF + 256)
#define SMEM_BYTES  (SMEM_FLOATS * 4)              // 218112

#define NCHUNK 18   // layer0: g 0..1, layer1: g 2..9, layer2: g 10..17

struct LevelParams { float scale[NLEV]; int res[NLEV]; int size[NLEV]; };

__device__ float g_W0r[64 * 256];
__device__ float g_W1r[256 * 256];
__device__ float g_W2r[256 * 256];

// ------------------------------- helpers -----------------------------------
__device__ __forceinline__ uint32_t smem_u32(const void* p) {
    uint32_t a;
    asm("{ .reg .u64 t; cvta.to.shared.u64 t, %1; cvt.u32.u64 %0, t; }"
        : "=r"(a) : "l"(p));
    return a;
}
__device__ __forceinline__ uint32_t tf32r(float f) {
    uint32_t u;
    asm("cvt.rna.tf32.f32 %0, %1;" : "=r"(u) : "f"(f));
    return u;
}
__device__ __forceinline__ void cp_async16(uint32_t dst, const void* src) {
    asm volatile("cp.async.cg.shared.global [%0], [%1], 16;" :: "r"(dst), "l"(src));
}
#define CP_COMMIT() asm volatile("cp.async.commit_group;" ::: "memory")
#define CP_WAIT1()  asm volatile("cp.async.wait_group 1;" ::: "memory")
#define CP_WAIT0()  asm volatile("cp.async.wait_group 0;" ::: "memory")

__device__ __forceinline__ void mma_tf32(float* d, const uint32_t* a,
                                         uint32_t b0, uint32_t b1) {
    asm volatile(
        "mma.sync.aligned.m16n8k8.row.col.f32.tf32.tf32.f32 "
        "{%0,%1,%2,%3}, {%4,%5,%6,%7}, {%8,%9}, {%0,%1,%2,%3};"
        : "+f"(d[0]), "+f"(d[1]), "+f"(d[2]), "+f"(d[3])
        : "r"(a[0]), "r"(a[1]), "r"(a[2]), "r"(a[3]), "r"(b0), "r"(b1));
}

// ------------------------------ prep: round weights -------------------------
__global__ void wt_round(const float* __restrict__ W0,
                         const float* __restrict__ W1,
                         const float* __restrict__ W2)
{
    int i = blockIdx.x * 256 + threadIdx.x;        // 0 .. 65535
    if (i < 64 * 256) g_W0r[i] = __uint_as_float(tf32r(W0[i]));
    g_W1r[i] = __uint_as_float(tf32r(W1[i]));
    g_W2r[i] = __uint_as_float(tf32r(W2[i]));
}

// --------------------------------- main kernel ------------------------------
__device__ __forceinline__ void prefetch_chunk(int g, uint32_t bs_base, int tid)
{
    const float* src;
    if (g < 2)       src = g_W0r + g * 32 * 256;
    else if (g < 10) src = g_W1r + (g - 2) * 32 * 256;
    else             src = g_W2r + (g - 10) * 32 * 256;
    const uint32_t dst = bs_base + (uint32_t)(g & 1) * (BS_F * 4);
    #pragma unroll
    for (int it = 0; it < 8; ++it) {
        const int i  = tid + it * 256;   // 0..2047 float4s
        const int r  = i >> 6;           // k-row 0..31
        const int c4 = i & 63;           // n float4 0..63
        cp_async16(dst + (uint32_t)(r * (HB_PITCH * 4) + c4 * 16),
                   src + r * 256 + c4 * 4);
    }
    CP_COMMIT();
}

__global__ __launch_bounds__(THREADS, 1)
void nf_main(const float* __restrict__ x, const float* __restrict__ table,
             const float* __restrict__ W3, float* __restrict__ out, LevelParams lp)
{
    extern __shared__ float smem[];
    float* hA  = smem + HA_OFF;
    float* B1  = smem + B1_OFF;
    float* B2  = smem + B2_OFF;
    float* W3s = smem + W3_OFF;
    const uint32_t bs_base = smem_u32(smem + BS_OFF);

    const int tid  = threadIdx.x;
    const int wid  = tid >> 5;
    const int lane = tid & 31;
    const int grp  = lane >> 2;          // 0..7
    const int tig  = lane & 3;           // 0..3

    // kick off weight chunk 0 immediately (overlaps encode)
    prefetch_chunk(0, bs_base, tid);

    W3s[tid] = W3[tid];

    // ---------------- Encode: 4 threads/point, 2 levels/thread --------------
    {
        const int p    = tid & 63;
        const int pair = tid >> 6;       // 0..3 -> levels {2p, 2p+1}
        const int gp   = blockIdx.x * 64 + p;
        const float xx = x[2 * gp];
        const float yy = x[2 * gp + 1];

        #pragma unroll
        for (int li = 0; li < 2; ++li) {
            const int l     = pair * 2 + li;
            const float s   = lp.scale[l];
            const int res   = lp.res[l];
            const int size  = lp.size[l];

            const float posx = xx * s + 0.5f;
            const float posy = yy * s + 0.5f;
            const float gx = floorf(posx), gy = floorf(posy);
            const float fx = posx - gx,    fy = posy - gy;
            const int   ix = (int)gx,      iy = (int)gy;
            const float wx = fx * fx * (3.0f - 2.0f * fx);
            const float wy = fy * fy * (3.0f - 2.0f * fy);

            float f[8];
            #pragma unroll
            for (int j = 0; j < 8; ++j) f[j] = 0.0f;

            #pragma unroll
            for (int dx = 0; dx < 2; ++dx) {
                const float wxx = dx ? wx : (1.0f - wx);
                #pragma unroll
                for (int dy = 0; dy < 2; ++dy) {
                    const float wyy = dy ? wy : (1.0f - wy);
                    const int idx = ((ix + dx) + (iy + dy) * res) % size;
                    const float4* tp =
                        (const float4*)(table + ((size_t)(l * 8192 + idx) << 3));
                    const float w = wxx * wyy;
                    const float4 t0 = tp[0];
                    const float4 t1 = tp[1];
                    f[0] += w * t0.x; f[1] += w * t0.y;
                    f[2] += w * t0.z; f[3] += w * t0.w;
                    f[4] += w * t1.x; f[5] += w * t1.y;
                    f[6] += w * t1.z; f[7] += w * t1.w;
                }
            }
            #pragma unroll
            for (int j = 0; j < 8; ++j)
                hA[p * HA_PITCH + l * 8 + j] = __uint_as_float(tf32r(f[j]));
        }
    }

    // ---------------- 3 GEMM layers on mma.sync TF32 -------------------------
    int g = 0;
    for (int layer = 0; layer < 3; ++layer) {
        const float* Aact = (layer == 0) ? hA : ((layer == 1) ? B1 : B2);
        float*       Cout = (layer == 1) ? B2 : B1;
        const int apitch  = (layer == 0) ? HA_PITCH : HB_PITCH;
        const int C       = (layer == 0) ? 2 : 8;

        float acc[4][4][4];
        #pragma unroll
        for (int mt = 0; mt < 4; ++mt)
            #pragma unroll
            for (int nt = 0; nt < 4; ++nt)
                #pragma unroll
                for (int q = 0; q < 4; ++q) acc[mt][nt][q] = 0.0f;

        for (int c = 0; c < C; ++c, ++g) {
            if (g + 1 < NCHUNK) { prefetch_chunk(g + 1, bs_base, tid); CP_WAIT1(); }
            else                { CP_WAIT0(); }
            __syncthreads();                       // Bs[g&1] ready everywhere

            const uint32_t* Bs =
                (const uint32_t*)(smem + BS_OFF + (g & 1) * BS_F);
            const uint32_t* Au = (const uint32_t*)Aact;

            #pragma unroll
            for (int kk = 0; kk < 32; kk += 8) {
                const int kcol = c * 32 + kk + tig;
                uint32_t a[4][4];
                #pragma unroll
                for (int mt = 0; mt < 4; ++mt) {
                    const int base = (mt * 16 + grp) * apitch + kcol;
                    a[mt][0] = Au[base];
                    a[mt][1] = Au[base + 8 * apitch];
                    a[mt][2] = Au[base + 4];
                    a[mt][3] = Au[base + 8 * apitch + 4];
                }
                #pragma unroll
                for (int nt = 0; nt < 4; ++nt) {
                    const int colb = wid * 32 + nt * 8 + grp;
                    const uint32_t b0 = Bs[(kk + tig) * HB_PITCH + colb];
                    const uint32_t b1 = Bs[(kk + 4 + tig) * HB_PITCH + colb];
                    #pragma unroll
                    for (int mt = 0; mt < 4; ++mt)
                        mma_tf32(acc[mt][nt], a[mt], b0, b1);
                }
            }
            __syncthreads();                       // done with Bs[g&1]
        }

        // epilogue: ReLU (+ tf32 round for layers feeding another GEMM)
        #pragma unroll
        for (int mt = 0; mt < 4; ++mt)
            #pragma unroll
            for (int nt = 0; nt < 4; ++nt) {
                const int r0 = mt * 16 + grp;
                const int c0 = wid * 32 + nt * 8 + tig * 2;
                float v0 = fmaxf(acc[mt][nt][0], 0.0f);
                float v1 = fmaxf(acc[mt][nt][1], 0.0f);
                float v2 = fmaxf(acc[mt][nt][2], 0.0f);
                float v3 = fmaxf(acc[mt][nt][3], 0.0f);
                if (layer < 2) {
                    v0 = __uint_as_float(tf32r(v0));
                    v1 = __uint_as_float(tf32r(v1));
                    v2 = __uint_as_float(tf32r(v2));
                    v3 = __uint_as_float(tf32r(v3));
                }
                Cout[r0 * HB_PITCH + c0]           = v0;
                Cout[r0 * HB_PITCH + c0 + 1]       = v1;
                Cout[(r0 + 8) * HB_PITCH + c0]     = v2;
                Cout[(r0 + 8) * HB_PITCH + c0 + 1] = v3;
            }
    }
    __syncthreads();

    // ---------------- Final: relu(h3) . W3, 4 threads/row --------------------
    {
        const int row = tid >> 2;
        const int seg = tid & 3;
        const float* h = B1 + row * HB_PITCH + seg * 64;
        const float* w = W3s + seg * 64;
        float s = 0.0f;
        #pragma unroll 16
        for (int k = 0; k < 64; ++k)
            s = fmaf(h[k], w[k], s);
        s += __shfl_xor_sync(0xffffffffu, s, 1);
        s += __shfl_xor_sync(0xffffffffu, s, 2);
        if (seg == 0) out[blockIdx.x * 64 + row] = s;
    }
}

// --------------------------------- launcher ---------------------------------
extern "C" void kernel_launch(void* const* d_in, const int* in_sizes, int n_in,
                              void* d_out, int out_size)
{
    const float* x     = (const float*)d_in[0];
    const float* table = (const float*)d_in[1];
    const float* W0    = (const float*)d_in[2];
    const float* W1    = (const float*)d_in[3];
    const float* W2    = (const float*)d_in[4];
    const float* W3    = (const float*)d_in[5];
    float*       out   = (float*)d_out;

    LevelParams lp;
    for (int l = 0; l < NLEV; ++l) {
        double sc = 16.0 * pow(1.2599210739135742, (double)l) - 1.0;
        int res = (int)ceil(sc) + 1;
        long long sz = (long long)res * (long long)res;
        sz = ((sz + 7) / 8) * 8;
        if (sz > (1LL << 19)) sz = 1LL << 19;
        lp.scale[l] = (float)sc;
        lp.res[l]   = res;
        lp.size[l]  = (int)sz;
    }

    wt_round<<<256, 256>>>(W0, W1, W2);

    cudaFuncSetAttribute(nf_main, cudaFuncAttributeMaxDynamicSharedMemorySize,
                         SMEM_BYTES);
    nf_main<<<NPTS / 64, THREADS, SMEM_BYTES>>>(x, table, W3, out, lp);
}

// round 5
// speedup vs baseline: 3.4791x; 1.2846x over previous
#include <cuda_runtime.h>
#include <cstdint>
#include <math.h>

// NeuralField fused: hashgrid encode + 3-layer MLP on mma.sync TF32 + final dot.
// CTA = 128 points, 256 threads (8 warps). Warp partition: 2 M-halves x 4
// N-quarters (64 rows x 64 cols per warp, acc[4][8][4]).
// Single in-place activation buffer (read-phase -> barrier -> write-phase),
// encode buffer aliased into it. Weights tf32-rounded in prep kernel,
// streamed as 32-row chunks via cp.async double-buffer. 1 sync per chunk.

#define NLEV    8
#define NPTS    262144
#define THREADS 256

#define HA_PITCH 68
#define HB_PITCH 268          // A-reads: bank 12g+t distinct; B-reads: 12t+g distinct

// float offsets in dynamic smem
#define B1_OFF   0                           // 128 x 268 activations (hA aliases here)
#define BS_OFF   (128 * HB_PITCH)            // 34304
#define BS_F     (32 * HB_PITCH)             // 8576 per buffer
#define W3_OFF   (BS_OFF + 2 * BS_F)         // 51456
#define SMEM_FLOATS (W3_OFF + 256)
#define SMEM_BYTES  (SMEM_FLOATS * 4)        // 206848

#define NCHUNK 18  // layer0: g 0..1 (K=64), layer1: 2..9, layer2: 10..17

struct LevelParams { float scale[NLEV]; int res[NLEV]; int size[NLEV]; };

__device__ float g_W0r[64 * 256];
__device__ float g_W1r[256 * 256];
__device__ float g_W2r[256 * 256];

// ------------------------------- helpers -----------------------------------
__device__ __forceinline__ uint32_t smem_u32(const void* p) {
    uint32_t a;
    asm("{ .reg .u64 t; cvta.to.shared.u64 t, %1; cvt.u32.u64 %0, t; }"
        : "=r"(a) : "l"(p));
    return a;
}
__device__ __forceinline__ uint32_t tf32r(float f) {
    uint32_t u;
    asm("cvt.rna.tf32.f32 %0, %1;" : "=r"(u) : "f"(f));
    return u;
}
__device__ __forceinline__ void cp_async16(uint32_t dst, const void* src) {
    asm volatile("cp.async.cg.shared.global [%0], [%1], 16;" :: "r"(dst), "l"(src));
}
#define CP_COMMIT() asm volatile("cp.async.commit_group;" ::: "memory")
#define CP_WAIT0()  asm volatile("cp.async.wait_group 0;" ::: "memory")

__device__ __forceinline__ void mma_tf32(float* d, const uint32_t* a,
                                         uint32_t b0, uint32_t b1) {
    asm volatile(
        "mma.sync.aligned.m16n8k8.row.col.f32.tf32.tf32.f32 "
        "{%0,%1,%2,%3}, {%4,%5,%6,%7}, {%8,%9}, {%0,%1,%2,%3};"
        : "+f"(d[0]), "+f"(d[1]), "+f"(d[2]), "+f"(d[3])
        : "r"(a[0]), "r"(a[1]), "r"(a[2]), "r"(a[3]), "r"(b0), "r"(b1));
}

// ------------------------------ prep: round weights -------------------------
__global__ void wt_round(const float* __restrict__ W0,
                         const float* __restrict__ W1,
                         const float* __restrict__ W2)
{
    int i = blockIdx.x * 256 + threadIdx.x;        // 0 .. 65535
    if (i < 64 * 256) g_W0r[i] = __uint_as_float(tf32r(W0[i]));
    g_W1r[i] = __uint_as_float(tf32r(W1[i]));
    g_W2r[i] = __uint_as_float(tf32r(W2[i]));
}

// --------------------------------- main kernel ------------------------------
__device__ __forceinline__ void prefetch_chunk(int g, uint32_t bs_base, int tid)
{
    const float* src;
    if (g < 2)       src = g_W0r + g * 32 * 256;
    else if (g < 10) src = g_W1r + (g - 2) * 32 * 256;
    else             src = g_W2r + (g - 10) * 32 * 256;
    const uint32_t dst = bs_base + (uint32_t)(g & 1) * (BS_F * 4);
    #pragma unroll
    for (int it = 0; it < 8; ++it) {
        const int i  = tid + it * 256;   // 0..2047 float4s
        const int r  = i >> 6;           // k-row 0..31
        const int c4 = i & 63;           // n float4 0..63
        cp_async16(dst + (uint32_t)(r * (HB_PITCH * 4) + c4 * 16),
                   src + r * 256 + c4 * 4);
    }
    CP_COMMIT();
}

__global__ __launch_bounds__(THREADS, 1)
void nf_main(const float* __restrict__ x, const float* __restrict__ table,
             const float* __restrict__ W3, float* __restrict__ out, LevelParams lp)
{
    extern __shared__ float smem[];
    float* B1  = smem + B1_OFF;          // activations (and encode alias, pitch 68)
    float* W3s = smem + W3_OFF;
    const uint32_t bs_base = smem_u32(smem + BS_OFF);

    const int tid  = threadIdx.x;
    const int wid  = tid >> 5;
    const int lane = tid & 31;
    const int grp  = lane >> 2;          // 0..7
    const int tig  = lane & 3;           // 0..3
    const int mb   = (wid & 1) * 64;     // M-half base row
    const int nb   = (wid >> 1) * 64;    // N-quarter base col

    prefetch_chunk(0, bs_base, tid);     // overlaps encode

    W3s[tid] = W3[tid];

    // ---------------- Encode: 2 threads/point, 4 levels/thread --------------
    {
        const int p    = tid & 127;
        const int half = tid >> 7;           // 0/1 -> levels 4h..4h+3
        const int gp   = blockIdx.x * 128 + p;
        const float xx = x[2 * gp];
        const float yy = x[2 * gp + 1];

        #pragma unroll
        for (int li = 0; li < 4; ++li) {
            const int l     = half * 4 + li;
            const float s   = lp.scale[l];
            const int res   = lp.res[l];
            const int size  = lp.size[l];

            const float posx = xx * s + 0.5f;
            const float posy = yy * s + 0.5f;
            const float gx = floorf(posx), gy = floorf(posy);
            const float fx = posx - gx,    fy = posy - gy;
            const int   ix = (int)gx,      iy = (int)gy;
            const float wx = fx * fx * (3.0f - 2.0f * fx);
            const float wy = fy * fy * (3.0f - 2.0f * fy);

            float f[8];
            #pragma unroll
            for (int j = 0; j < 8; ++j) f[j] = 0.0f;

            #pragma unroll
            for (int dx = 0; dx < 2; ++dx) {
                const float wxx = dx ? wx : (1.0f - wx);
                #pragma unroll
                for (int dy = 0; dy < 2; ++dy) {
                    const float wyy = dy ? wy : (1.0f - wy);
                    const int idx = ((ix + dx) + (iy + dy) * res) % size;
                    const float4* tp =
                        (const float4*)(table + ((size_t)(l * 8192 + idx) << 3));
                    const float w = wxx * wyy;
                    const float4 t0 = tp[0];
                    const float4 t1 = tp[1];
                    f[0] += w * t0.x; f[1] += w * t0.y;
                    f[2] += w * t0.z; f[3] += w * t0.w;
                    f[4] += w * t1.x; f[5] += w * t1.y;
                    f[6] += w * t1.z; f[7] += w * t1.w;
                }
            }
            float4 v0, v1;
            v0.x = __uint_as_float(tf32r(f[0])); v0.y = __uint_as_float(tf32r(f[1]));
            v0.z = __uint_as_float(tf32r(f[2])); v0.w = __uint_as_float(tf32r(f[3]));
            v1.x = __uint_as_float(tf32r(f[4])); v1.y = __uint_as_float(tf32r(f[5]));
            v1.z = __uint_as_float(tf32r(f[6])); v1.w = __uint_as_float(tf32r(f[7]));
            *(float4*)&B1[p * HA_PITCH + l * 8]     = v0;
            *(float4*)&B1[p * HA_PITCH + l * 8 + 4] = v1;
        }
    }

    // ---------------- 18 chunks across 3 layers ------------------------------
    float acc[4][8][4];
    #pragma unroll
    for (int mt = 0; mt < 4; ++mt)
        #pragma unroll
        for (int nt = 0; nt < 8; ++nt)
            #pragma unroll
            for (int q = 0; q < 4; ++q) acc[mt][nt][q] = 0.0f;

    for (int g = 0; g < NCHUNK; ++g) {
        CP_WAIT0();                 // chunk g's weights landed
        __syncthreads();            // visible to all; prev buffer reads done
        if (g + 1 < NCHUNK) prefetch_chunk(g + 1, bs_base, tid);

        const int layer = (g < 2) ? 0 : ((g < 10) ? 1 : 2);
        const int kc0   = 32 * ((layer == 0) ? g : ((layer == 1) ? g - 2 : g - 10));
        const int ap    = (layer == 0) ? HA_PITCH : HB_PITCH;
        const uint32_t* Au = (const uint32_t*)B1;
        const uint32_t* Bs = (const uint32_t*)(smem + BS_OFF + (g & 1) * BS_F);

        #pragma unroll
        for (int kk = 0; kk < 32; kk += 8) {
            const int kcol = kc0 + kk + tig;
            uint32_t a[4][4];
            #pragma unroll
            for (int mt = 0; mt < 4; ++mt) {
                const int base = (mb + mt * 16 + grp) * ap + kcol;
                a[mt][0] = Au[base];
                a[mt][1] = Au[base + 8 * ap];
                a[mt][2] = Au[base + 4];
                a[mt][3] = Au[base + 8 * ap + 4];
            }
            #pragma unroll
            for (int nt = 0; nt < 8; ++nt) {
                const int colb = nb + nt * 8 + grp;
                const uint32_t b0 = Bs[(kk + tig) * HB_PITCH + colb];
                const uint32_t b1 = Bs[(kk + 4 + tig) * HB_PITCH + colb];
                #pragma unroll
                for (int mt = 0; mt < 4; ++mt)
                    mma_tf32(acc[mt][nt], a[mt], b0, b1);
            }
        }

        if (g == 1 || g == 9 || g == 17) {
            __syncthreads();        // all reads of B1 done -> in-place write OK
            const bool last = (g == 17);
            #pragma unroll
            for (int mt = 0; mt < 4; ++mt)
                #pragma unroll
                for (int nt = 0; nt < 8; ++nt) {
                    const int r0 = mb + mt * 16 + grp;
                    const int c0 = nb + nt * 8 + tig * 2;
                    float v0 = fmaxf(acc[mt][nt][0], 0.0f);
                    float v1 = fmaxf(acc[mt][nt][1], 0.0f);
                    float v2 = fmaxf(acc[mt][nt][2], 0.0f);
                    float v3 = fmaxf(acc[mt][nt][3], 0.0f);
                    if (!last) {
                        v0 = __uint_as_float(tf32r(v0));
                        v1 = __uint_as_float(tf32r(v1));
                        v2 = __uint_as_float(tf32r(v2));
                        v3 = __uint_as_float(tf32r(v3));
                    }
                    B1[r0 * HB_PITCH + c0]           = v0;
                    B1[r0 * HB_PITCH + c0 + 1]       = v1;
                    B1[(r0 + 8) * HB_PITCH + c0]     = v2;
                    B1[(r0 + 8) * HB_PITCH + c0 + 1] = v3;
                    acc[mt][nt][0] = 0.0f; acc[mt][nt][1] = 0.0f;
                    acc[mt][nt][2] = 0.0f; acc[mt][nt][3] = 0.0f;
                }
        }
    }
    __syncthreads();

    // ---------------- Final: relu(h3) . W3, 2 threads/row --------------------
    {
        const int row = tid >> 1;
        const int seg = tid & 1;
        const float* h = B1 + row * HB_PITCH + seg * 128;
        const float* w = W3s + seg * 128;
        float s = 0.0f;
        #pragma unroll 16
        for (int k = 0; k < 128; ++k)
            s = fmaf(h[k], w[k], s);
        s += __shfl_xor_sync(0xffffffffu, s, 1);
        if (seg == 0) out[blockIdx.x * 128 + row] = s;
    }
}

// --------------------------------- launcher ---------------------------------
extern "C" void kernel_launch(void* const* d_in, const int* in_sizes, int n_in,
                              void* d_out, int out_size)
{
    const float* x     = (const float*)d_in[0];
    const float* table = (const float*)d_in[1];
    const float* W0    = (const float*)d_in[2];
    const float* W1    = (const float*)d_in[3];
    const float* W2    = (const float*)d_in[4];
    const float* W3    = (const float*)d_in[5];
    float*       out   = (float*)d_out;

    LevelParams lp;
    for (int l = 0; l < NLEV; ++l) {
        double sc = 16.0 * pow(1.2599210739135742, (double)l) - 1.0;
        int res = (int)ceil(sc) + 1;
        long long sz = (long long)res * (long long)res;
        sz = ((sz + 7) / 8) * 8;
        if (sz > (1LL << 19)) sz = 1LL << 19;
        lp.scale[l] = (float)sc;
        lp.res[l]   = res;
        lp.size[l]  = (int)sz;
    }

    wt_round<<<256, 256>>>(W0, W1, W2);

    cudaFuncSetAttribute(nf_main, cudaFuncAttributeMaxDynamicSharedMemorySize,
                         SMEM_BYTES);
    nf_main<<<NPTS / 128, THREADS, SMEM_BYTES>>>(x, table, W3, out, lp);
}

// round 6
// speedup vs baseline: 3.8697x; 1.1123x over previous
#include <cuda_runtime.h>
#include <cstdint>
#include <math.h>

// NeuralField fused: hashgrid encode + 3-layer MLP on mma.sync TF32 + final dot.
// CTA = 128 points, 256 threads (8 warps), warp tile 64x64 (2 M-halves x 4 N-qtrs).
// This round: fragment-native SMEM layouts.
//  - A: k-permuted (slot tig <-> phys 2tig, slot tig+4 <-> phys 2tig+1) -> LDS.64
//  - B: prep kernel pre-gathers weights into per-thread fragment order -> LDS.128,
//       cp.async is a straight contiguous 32KB copy per chunk.

#define NLEV    8
#define NPTS    262144
#define THREADS 256

#define HA_PITCH 72           // 72 % 32 == 8 -> conflict-free LDS.64
#define HB_PITCH 264          // 264 % 32 == 8

#define B1_OFF   0                           // 128 x 264 activations (+ encode alias)
#define BS_OFF   (128 * HB_PITCH)            // 33792
#define BS_F     8192                        // fragment-major chunk: 32KB
#define W3_OFF   (BS_OFF + 2 * BS_F)         // 50176
#define SMEM_FLOATS (W3_OFF + 256)
#define SMEM_BYTES  (SMEM_FLOATS * 4)        // 201728

#define NCHUNK 18  // layer0: g 0..1 (K=64), layer1: 2..9, layer2: 10..17

struct LevelParams { float scale[NLEV]; int res[NLEV]; int size[NLEV]; };

// fragment-major weights: [18][nq(4)][kk(4)][j(4)][lane(32)][e(4)]
__device__ float g_Wf[18 * BS_F];

// ------------------------------- helpers -----------------------------------
__device__ __forceinline__ uint32_t smem_u32(const void* p) {
    uint32_t a;
    asm("{ .reg .u64 t; cvta.to.shared.u64 t, %1; cvt.u32.u64 %0, t; }"
        : "=r"(a) : "l"(p));
    return a;
}
__device__ __forceinline__ uint32_t tf32r(float f) {
    uint32_t u;
    asm("cvt.rna.tf32.f32 %0, %1;" : "=r"(u) : "f"(f));
    return u;
}
__device__ __forceinline__ void cp_async16(uint32_t dst, const void* src) {
    asm volatile("cp.async.cg.shared.global [%0], [%1], 16;" :: "r"(dst), "l"(src));
}
#define CP_COMMIT() asm volatile("cp.async.commit_group;" ::: "memory")
#define CP_WAIT0()  asm volatile("cp.async.wait_group 0;" ::: "memory")

__device__ __forceinline__ void mma_tf32(float* d, const uint32_t* a,
                                         uint32_t b0, uint32_t b1) {
    asm volatile(
        "mma.sync.aligned.m16n8k8.row.col.f32.tf32.tf32.f32 "
        "{%0,%1,%2,%3}, {%4,%5,%6,%7}, {%8,%9}, {%0,%1,%2,%3};"
        : "+f"(d[0]), "+f"(d[1]), "+f"(d[2]), "+f"(d[3])
        : "r"(a[0]), "r"(a[1]), "r"(a[2]), "r"(a[3]), "r"(b0), "r"(b1));
}

// ---------------- prep: gather weights into fragment order + tf32 -----------
__global__ void wt_prep(const float* __restrict__ W0,
                        const float* __restrict__ W1,
                        const float* __restrict__ W2)
{
    const int idx = blockIdx.x * 256 + threadIdx.x;    // 0 .. 147455
    const int g    = idx >> 13;
    const int r    = idx & 8191;
    const int nq   = r >> 11;
    const int kkI  = (r >> 9) & 3;
    const int j    = (r >> 7) & 3;
    const int lane = (r >> 2) & 31;
    const int e    = r & 3;
    const int grp  = lane >> 2, tig = lane & 3;
    const int i16  = j * 4 + e;
    const int nt   = i16 >> 1;
    const int b    = i16 & 1;

    const float* W; int kc;
    if (g < 2)       { W = W0; kc = g * 32; }
    else if (g < 10) { W = W1; kc = (g - 2) * 32; }
    else             { W = W2; kc = (g - 10) * 32; }

    const int k = kc + kkI * 8 + 2 * tig + b;          // k-permuted slot
    const int n = nq * 64 + nt * 8 + grp;
    g_Wf[idx] = __uint_as_float(tf32r(W[k * 256 + n]));
}

// --------------------------------- main kernel ------------------------------
__device__ __forceinline__ void prefetch_chunk(int g, uint32_t bs_base, int tid)
{
    const float* src = g_Wf + g * BS_F;
    const uint32_t dst = bs_base + (uint32_t)(g & 1) * (BS_F * 4);
    #pragma unroll
    for (int it = 0; it < 8; ++it) {
        const int i = tid + it * 256;                  // 0..2047 float4s, contiguous
        cp_async16(dst + (uint32_t)i * 16, src + i * 4);
    }
    CP_COMMIT();
}

__global__ __launch_bounds__(THREADS, 1)
void nf_main(const float* __restrict__ x, const float* __restrict__ table,
             const float* __restrict__ W3, float* __restrict__ out, LevelParams lp)
{
    extern __shared__ float smem[];
    float* B1  = smem + B1_OFF;
    float* W3s = smem + W3_OFF;
    const uint32_t bs_base = smem_u32(smem + BS_OFF);

    const int tid  = threadIdx.x;
    const int wid  = tid >> 5;
    const int lane = tid & 31;
    const int grp  = lane >> 2;
    const int tig  = lane & 3;
    const int mb   = (wid & 1) * 64;
    const int nq   = wid >> 1;
    const int nb   = nq * 64;

    prefetch_chunk(0, bs_base, tid);     // overlaps encode

    W3s[tid] = W3[tid];

    // ---------------- Encode: 2 threads/point, 4 levels/thread --------------
    {
        const int p    = tid & 127;
        const int half = tid >> 7;
        const int gp   = blockIdx.x * 128 + p;
        const float xx = x[2 * gp];
        const float yy = x[2 * gp + 1];

        #pragma unroll
        for (int li = 0; li < 4; ++li) {
            const int l     = half * 4 + li;
            const float s   = lp.scale[l];
            const int res   = lp.res[l];
            const int size  = lp.size[l];

            const float posx = xx * s + 0.5f;
            const float posy = yy * s + 0.5f;
            const float gx = floorf(posx), gy = floorf(posy);
            const float fx = posx - gx,    fy = posy - gy;
            const int   ix = (int)gx,      iy = (int)gy;
            const float wx = fx * fx * (3.0f - 2.0f * fx);
            const float wy = fy * fy * (3.0f - 2.0f * fy);

            float f[8];
            #pragma unroll
            for (int j = 0; j < 8; ++j) f[j] = 0.0f;

            #pragma unroll
            for (int dx = 0; dx < 2; ++dx) {
                const float wxx = dx ? wx : (1.0f - wx);
                #pragma unroll
                for (int dy = 0; dy < 2; ++dy) {
                    const float wyy = dy ? wy : (1.0f - wy);
                    const int idx = ((ix + dx) + (iy + dy) * res) % size;
                    const float4* tp =
                        (const float4*)(table + ((size_t)(l * 8192 + idx) << 3));
                    const float w = wxx * wyy;
                    const float4 t0 = tp[0];
                    const float4 t1 = tp[1];
                    f[0] += w * t0.x; f[1] += w * t0.y;
                    f[2] += w * t0.z; f[3] += w * t0.w;
                    f[4] += w * t1.x; f[5] += w * t1.y;
                    f[6] += w * t1.z; f[7] += w * t1.w;
                }
            }
            float4 v0, v1;
            v0.x = __uint_as_float(tf32r(f[0])); v0.y = __uint_as_float(tf32r(f[1]));
            v0.z = __uint_as_float(tf32r(f[2])); v0.w = __uint_as_float(tf32r(f[3]));
            v1.x = __uint_as_float(tf32r(f[4])); v1.y = __uint_as_float(tf32r(f[5]));
            v1.z = __uint_as_float(tf32r(f[6])); v1.w = __uint_as_float(tf32r(f[7]));
            *(float4*)&B1[p * HA_PITCH + l * 8]     = v0;
            *(float4*)&B1[p * HA_PITCH + l * 8 + 4] = v1;
        }
    }

    // ---------------- 18 chunks across 3 layers ------------------------------
    float acc[4][8][4];
    #pragma unroll
    for (int mt = 0; mt < 4; ++mt)
        #pragma unroll
        for (int nt = 0; nt < 8; ++nt)
            #pragma unroll
            for (int q = 0; q < 4; ++q) acc[mt][nt][q] = 0.0f;

    for (int g = 0; g < NCHUNK; ++g) {
        CP_WAIT0();
        __syncthreads();
        if (g + 1 < NCHUNK) prefetch_chunk(g + 1, bs_base, tid);

        const int layer = (g < 2) ? 0 : ((g < 10) ? 1 : 2);
        const int kc0   = 32 * ((layer == 0) ? g : ((layer == 1) ? g - 2 : g - 10));
        const int ap    = (layer == 0) ? HA_PITCH : HB_PITCH;
        const float* Bs = smem + BS_OFF + (g & 1) * BS_F;

        #pragma unroll
        for (int kkI = 0; kkI < 4; ++kkI) {
            // A fragments: LDS.64 pairs (phys cols 2tig, 2tig+1)
            const int acol = kc0 + kkI * 8 + 2 * tig;
            uint32_t a[4][4];
            #pragma unroll
            for (int mt = 0; mt < 4; ++mt) {
                const int r0 = (mb + mt * 16 + grp) * ap + acol;
                const float2 p0 = *(const float2*)&B1[r0];
                const float2 p1 = *(const float2*)&B1[r0 + 8 * ap];
                a[mt][0] = __float_as_uint(p0.x);
                a[mt][1] = __float_as_uint(p1.x);
                a[mt][2] = __float_as_uint(p0.y);
                a[mt][3] = __float_as_uint(p1.y);
            }
            // B fragments: 4x LDS.128, fragment-major, conflict-free
            float bf[16];
            #pragma unroll
            for (int j = 0; j < 4; ++j)
                *(float4*)&bf[j * 4] =
                    *(const float4*)&Bs[((nq * 4 + kkI) * 4 + j) * 128 + lane * 4];

            #pragma unroll
            for (int nt = 0; nt < 8; ++nt) {
                const uint32_t b0 = __float_as_uint(bf[nt * 2]);
                const uint32_t b1 = __float_as_uint(bf[nt * 2 + 1]);
                #pragma unroll
                for (int mt = 0; mt < 4; ++mt)
                    mma_tf32(acc[mt][nt], a[mt], b0, b1);
            }
        }

        if (g == 1 || g == 9 || g == 17) {
            __syncthreads();        // all reads of B1 done -> in-place write OK
            const bool last = (g == 17);
            #pragma unroll
            for (int mt = 0; mt < 4; ++mt)
                #pragma unroll
                for (int nt = 0; nt < 8; ++nt) {
                    const int r0 = mb + mt * 16 + grp;
                    const int c0 = nb + nt * 8 + tig * 2;
                    float v0 = fmaxf(acc[mt][nt][0], 0.0f);
                    float v1 = fmaxf(acc[mt][nt][1], 0.0f);
                    float v2 = fmaxf(acc[mt][nt][2], 0.0f);
                    float v3 = fmaxf(acc[mt][nt][3], 0.0f);
                    if (!last) {
                        v0 = __uint_as_float(tf32r(v0));
                        v1 = __uint_as_float(tf32r(v1));
                        v2 = __uint_as_float(tf32r(v2));
                        v3 = __uint_as_float(tf32r(v3));
                    }
                    float2 w01; w01.x = v0; w01.y = v1;
                    float2 w23; w23.x = v2; w23.y = v3;
                    *(float2*)&B1[r0 * HB_PITCH + c0]       = w01;
                    *(float2*)&B1[(r0 + 8) * HB_PITCH + c0] = w23;
                    acc[mt][nt][0] = 0.0f; acc[mt][nt][1] = 0.0f;
                    acc[mt][nt][2] = 0.0f; acc[mt][nt][3] = 0.0f;
                }
        }
    }
    __syncthreads();

    // ---------------- Final: relu(h3) . W3, 2 threads/row --------------------
    {
        const int row = tid >> 1;
        const int seg = tid & 1;
        const float* h = B1 + row * HB_PITCH + seg * 128;
        const float* w = W3s + seg * 128;
        float s = 0.0f;
        #pragma unroll 16
        for (int k = 0; k < 128; ++k)
            s = fmaf(h[k], w[k], s);
        s += __shfl_xor_sync(0xffffffffu, s, 1);
        if (seg == 0) out[blockIdx.x * 128 + row] = s;
    }
}

// --------------------------------- launcher ---------------------------------
extern "C" void kernel_launch(void* const* d_in, const int* in_sizes, int n_in,
                              void* d_out, int out_size)
{
    const float* x     = (const float*)d_in[0];
    const float* table = (const float*)d_in[1];
    const float* W0    = (const float*)d_in[2];
    const float* W1    = (const float*)d_in[3];
    const float* W2    = (const float*)d_in[4];
    const float* W3    = (const float*)d_in[5];
    float*       out   = (float*)d_out;

    LevelParams lp;
    for (int l = 0; l < NLEV; ++l) {
        double sc = 16.0 * pow(1.2599210739135742, (double)l) - 1.0;
        int res = (int)ceil(sc) + 1;
        long long sz = (long long)res * (long long)res;
        sz = ((sz + 7) / 8) * 8;
        if (sz > (1LL << 19)) sz = 1LL << 19;
        lp.scale[l] = (float)sc;
        lp.res[l]   = res;
        lp.size[l]  = (int)sz;
    }

    wt_prep<<<576, 256>>>(W0, W1, W2);

    cudaFuncSetAttribute(nf_main, cudaFuncAttributeMaxDynamicSharedMemorySize,
                         SMEM_BYTES);
    nf_main<<<NPTS / 128, THREADS, SMEM_BYTES>>>(x, table, W3, out, lp);
}